// round 6
// baseline (speedup 1.0000x reference)
#include <cuda_runtime.h>

#define DD    32
#define PREV  64
#define HIDN  128
#define HDIM  64
#define NW    ((DD + 1) * PREV)   // 2112
#define BATCH 8192
#define RSTR  36   // smem row stride (floats); d0..15 @ +0, d16..31 @ +18, beff @ +34, c @ +35

typedef unsigned long long u64;

__device__ __forceinline__ u64 fma2(u64 a, u64 b, u64 c) {
    u64 d; asm("fma.rn.f32x2 %0,%1,%2,%3;" : "=l"(d) : "l"(a), "l"(b), "l"(c)); return d;
}
__device__ __forceinline__ u64 add2(u64 a, u64 b) {
    u64 d; asm("add.rn.f32x2 %0,%1,%2;" : "=l"(d) : "l"(a), "l"(b)); return d;
}
__device__ __forceinline__ u64 pack2(float lo, float hi) {
    u64 r; asm("mov.b64 %0,{%1,%2};" : "=l"(r) : "f"(lo), "f"(hi)); return r;
}
__device__ __forceinline__ float2 unpack2(u64 v) {
    float lo, hi; asm("mov.b64 {%0,%1},%2;" : "=f"(lo), "=f"(hi) : "l"(v));
    return make_float2(lo, hi);
}

// Batch-independent precomputed tensors.
__device__ float g_M[HIDN * DD];    // [h][d]  M = bw @ w1^T
__device__ float g_w2t[HIDN * DD];  // [h][d]  w2^T
__device__ float g_beff[HIDN];

// ---------------------------------------------------------------------------
// prep: 18 CTAs x 256 threads, fully parallel.
// ---------------------------------------------------------------------------
__global__ void __launch_bounds__(256)
prep_kernel(const float* __restrict__ t,   const float* __restrict__ hw1,
            const float* __restrict__ hb1, const float* __restrict__ hw2,
            const float* __restrict__ hb2, const float* __restrict__ bw,
            const float* __restrict__ bb,  const float* __restrict__ w2) {
    __shared__ float hcode[HDIM];
    __shared__ float w1s[2][66];
    __shared__ float b1s[PREV];
    __shared__ float bws[HIDN * 65];

    int tid = threadIdx.x, lane = tid & 31, wrp = tid >> 5;
    int cta = blockIdx.x;

    if (cta == 17) {   // transpose w2 [d][h] -> [h][d]
        for (int i = tid; i < HIDN * DD; i += 256) {
            int d = i >> 7, h = i & 127;
            g_w2t[h * DD + d] = w2[i];
        }
        return;
    }

    if (tid < HDIM)
        hcode[tid] = tanhf(t[0] * hw1[tid] + hb1[tid]);
    for (int i = tid; i < HIDN * PREV; i += 256)
        bws[(i >> 6) * 65 + (i & 63)] = bw[i];
    __syncthreads();

    if (cta < 16) {
        int rbase = cta * 128;
#pragma unroll
        for (int rr = wrp; rr < 128; rr += 8) {
            int r = rbase + rr;
            const float* row = hw2 + r * HDIM;
            float acc = hcode[lane] * row[lane] + hcode[lane + 32] * row[lane + 32];
#pragma unroll
            for (int m = 16; m >= 1; m >>= 1)
                acc += __shfl_xor_sync(0xffffffffu, acc, m);
            if (lane == 0) w1s[rr >> 6][rr & 63] = acc + hb2[r];
        }
        __syncthreads();
        int dl = tid & 1, h = tid >> 1;
        int d  = 2 * cta + dl;
        float m = 0.f;
#pragma unroll
        for (int p = 0; p < PREV; p++)
            m += bws[h * 65 + p] * w1s[dl][p];
        g_M[h * DD + d] = m;
    } else {
#pragma unroll
        for (int rr = wrp; rr < PREV; rr += 8) {
            int r = DD * PREV + rr;
            const float* row = hw2 + r * HDIM;
            float acc = hcode[lane] * row[lane] + hcode[lane + 32] * row[lane + 32];
#pragma unroll
            for (int m = 16; m >= 1; m >>= 1)
                acc += __shfl_xor_sync(0xffffffffu, acc, m);
            if (lane == 0) b1s[rr] = acc + hb2[r];
        }
        __syncthreads();
        if (tid < HIDN) {
            float be = bb[tid];
#pragma unroll
            for (int p = 0; p < PREV; p++)
                be += bws[tid * 65 + p] * b1s[p];
            g_beff[tid] = be;
        }
    }
}

// ---------------------------------------------------------------------------
// main: 256 CTAs x 256 threads, 32 rows/CTA, 2 rows/thread, d-split halves.
// THREE-PHASE body: (1) all 16 s-values (batched shfl merges),
// (2) all tanh (batched MUFU), (3) all W-accumulations.
// Each phase is 16 independent chains -> latency hidden at 16 warps/SM.
// ---------------------------------------------------------------------------
__global__ void __launch_bounds__(256, 2)
ode_main_kernel(const float* __restrict__ y,
                const float* __restrict__ b2,
                float* __restrict__ out) {
    __shared__ __align__(16) float Mt [HIDN * RSTR];
    __shared__ __align__(16) float W2t[HIDN * RSTR];
    __shared__ __align__(16) float xs [32 * RSTR];   // input tile; reused as output tile
    __shared__ float b2s[DD];

    int tid = threadIdx.x;

    // fill Mt / W2t d-regions (d -> d + 2*(d>=16) within each 36-float row)
    {
        const float4* ms = reinterpret_cast<const float4*>(g_M);
        const float4* ws = reinterpret_cast<const float4*>(g_w2t);
        for (int i = tid; i < HIDN * DD / 4; i += 256) {
            int col = i >> 3, q = i & 7;
            int off = col * RSTR + ((q < 4) ? 4 * q : 4 * q + 2);
            float4 mv = ms[i], wv = ws[i];
            *reinterpret_cast<float2*>(Mt  + off)     = make_float2(mv.x, mv.y);
            *reinterpret_cast<float2*>(Mt  + off + 2) = make_float2(mv.z, mv.w);
            *reinterpret_cast<float2*>(W2t + off)     = make_float2(wv.x, wv.y);
            *reinterpret_cast<float2*>(W2t + off + 2) = make_float2(wv.z, wv.w);
        }
    }
    if (tid < HIDN) Mt[tid * RSTR + 34] = g_beff[tid];
    if (tid < DD)   b2s[tid] = b2[tid];

    int rowbase = blockIdx.x * 32;
    for (int i = tid; i < 32 * 33; i += 256) {
        int r = i / 33, c = i - r * 33;
        xs[r * RSTR + c] = y[rowbase * 33 + i];
    }
    __syncthreads();

    // c[h] = sum_d M[h,d]*w2t[h,d]  -> Mt[h*RSTR+35]
    if (tid < HIDN) {
        const float* mr = Mt  + tid * RSTR;
        const float* wr = W2t + tid * RSTR;
        float c = 0.f;
#pragma unroll
        for (int k = 0; k < 16; k++) c += mr[k] * wr[k];
#pragma unroll
        for (int k = 18; k < 34; k++) c += mr[k] * wr[k];
        Mt[tid * RSTR + 35] = c;
    }
    __syncthreads();

    int g2 = tid & 7;
    int dh = (tid >> 3) & 1;
    int rw = tid >> 4;          // 0..15 -> rows 2rw, 2rw+1
    int moff = dh * 18;

    u64 xp0[8], xp1[8];
    {
        const float* xr0 = xs + (2 * rw)     * RSTR + dh * 16;
        const float* xr1 = xs + (2 * rw + 1) * RSTR + dh * 16;
#pragma unroll
        for (int j = 0; j < 8; j++) {
            xp0[j] = *reinterpret_cast<const u64*>(xr0 + 2 * j);
            xp1[j] = *reinterpret_cast<const u64*>(xr1 + 2 * j);
        }
    }

    // ---------------- phase 1: all 16 packed s-values ----------------
    u64 sp[16];
#pragma unroll
    for (int hh = 0; hh < 16; hh++) {
        int col = hh * 8 + g2;
        const u64* mr = reinterpret_cast<const u64*>(Mt + col * RSTR + moff);
        u64 a0 = 0ull, a1 = 0ull, b0 = 0ull, b1 = 0ull;
#pragma unroll
        for (int j = 0; j < 8; j += 2) {
            u64 m0 = mr[j], m1 = mr[j + 1];
            a0 = fma2(m0, xp0[j],     a0);
            a1 = fma2(m1, xp0[j + 1], a1);
            b0 = fma2(m0, xp1[j],     b0);
            b1 = fma2(m1, xp1[j + 1], b1);
        }
        float2 svA = unpack2(add2(a0, a1));
        float2 svB = unpack2(add2(b0, b1));
        sp[hh] = pack2(svA.x + svA.y, svB.x + svB.y);
    }
    // batched d-half merges (independent shfls, pipelined)
#pragma unroll
    for (int hh = 0; hh < 16; hh++)
        sp[hh] = add2(sp[hh], __shfl_xor_sync(0xffffffffu, sp[hh], 8));

    // ---------------- phase 2: all tanh + divergence terms ----------------
    float a0s[16], a1s[16];
    float dv0 = 0.f, dv1 = 0.f;
#pragma unroll
    for (int hh = 0; hh < 16; hh++) {
        int col = hh * 8 + g2;
        float be = Mt[col * RSTR + 34];
        float cc = Mt[col * RSTR + 35];
        float2 sv = unpack2(sp[hh]);
        float r0 = __fdividef(2.f, __expf(2.f * (sv.x + be)) + 1.f);
        float r1 = __fdividef(2.f, __expf(2.f * (sv.y + be)) + 1.f);
        a0s[hh] = 1.f - r0;
        a1s[hh] = 1.f - r1;
        dv0 += r0 * (2.f - r0) * cc;
        dv1 += r1 * (2.f - r1) * cc;
    }

    // ---------------- phase 3: all W accumulations ----------------
    u64 dxp0[8], dxp1[8];
#pragma unroll
    for (int j = 0; j < 8; j++) { dxp0[j] = 0ull; dxp1[j] = 0ull; }
#pragma unroll
    for (int hh = 0; hh < 16; hh++) {
        int col = hh * 8 + g2;
        u64 aa0 = pack2(a0s[hh], a0s[hh]);
        u64 aa1 = pack2(a1s[hh], a1s[hh]);
        const u64* wr = reinterpret_cast<const u64*>(W2t + col * RSTR + moff);
#pragma unroll
        for (int j = 0; j < 8; j++) {
            u64 wv = wr[j];
            dxp0[j] = fma2(wv, aa0, dxp0[j]);
            dxp1[j] = fma2(wv, aa1, dxp1[j]);
        }
    }

    // reduce over the 8 g2 groups (lane bits 0..2)
#pragma unroll
    for (int m = 1; m <= 4; m <<= 1) {
        u64 dvp = pack2(dv0, dv1);
        dvp = add2(dvp, __shfl_xor_sync(0xffffffffu, dvp, m));
        float2 dvv = unpack2(dvp);
        dv0 = dvv.x; dv1 = dvv.y;
#pragma unroll
        for (int j = 0; j < 8; j++) {
            dxp0[j] = add2(dxp0[j], __shfl_xor_sync(0xffffffffu, dxp0[j], m));
            dxp1[j] = add2(dxp1[j], __shfl_xor_sync(0xffffffffu, dxp1[j], m));
        }
    }

    __syncthreads();   // all xs input reads done; reuse xs as output tile
    if (g2 == 0) {
        float* o0 = xs + (2 * rw)     * RSTR + dh * 16;
        float* o1 = xs + (2 * rw + 1) * RSTR + dh * 16;
#pragma unroll
        for (int j = 0; j < 8; j++) {
            float2 v0 = unpack2(dxp0[j]);
            float2 v1 = unpack2(dxp1[j]);
            float bl = b2s[dh * 16 + 2 * j], bh = b2s[dh * 16 + 2 * j + 1];
            o0[2 * j] = v0.x + bl;  o0[2 * j + 1] = v0.y + bh;
            o1[2 * j] = v1.x + bl;  o1[2 * j + 1] = v1.y + bh;
        }
        if (dh == 0) {
            xs[(2 * rw)     * RSTR + 32] = -dv0;
            xs[(2 * rw + 1) * RSTR + 32] = -dv1;
        }
    }
    __syncthreads();
    for (int i = tid; i < 32 * 33; i += 256) {
        int r = i / 33, c = i - r * 33;
        out[rowbase * 33 + i] = xs[r * RSTR + c];
    }
}

// ---------------------------------------------------------------------------
// inputs: 0:y 1:t 2:hw1 3:hb1 4:hw2 5:hb2 6:bw 7:bb 8:w2 9:b2
// ---------------------------------------------------------------------------
extern "C" void kernel_launch(void* const* d_in, const int* in_sizes, int n_in,
                              void* d_out, int out_size) {
    const float* y   = (const float*)d_in[0];
    const float* t   = (const float*)d_in[1];
    const float* hw1 = (const float*)d_in[2];
    const float* hb1 = (const float*)d_in[3];
    const float* hw2 = (const float*)d_in[4];
    const float* hb2 = (const float*)d_in[5];
    const float* bw  = (const float*)d_in[6];
    const float* bb  = (const float*)d_in[7];
    const float* w2  = (const float*)d_in[8];
    const float* b2  = (const float*)d_in[9];
    float* out = (float*)d_out;

    prep_kernel<<<18, 256>>>(t, hw1, hb1, hw2, hb2, bw, bb, w2);
    ode_main_kernel<<<BATCH / 32, 256>>>(y, b2, out);
}

// round 7
// speedup vs baseline: 1.0558x; 1.0558x over previous
#include <cuda_runtime.h>

#define DD    32
#define PREV  64
#define HIDN  128
#define HDIM  64
#define NW    ((DD + 1) * PREV)   // 2112
#define BATCH 8192
#define RSTR  36   // smem row stride (floats); d0..15 @ +0, d16..31 @ +16, (beff,c) @ +32

typedef unsigned long long u64;

__device__ __forceinline__ u64 fma2(u64 a, u64 b, u64 c) {
    u64 d; asm("fma.rn.f32x2 %0,%1,%2,%3;" : "=l"(d) : "l"(a), "l"(b), "l"(c)); return d;
}
__device__ __forceinline__ u64 add2(u64 a, u64 b) {
    u64 d; asm("add.rn.f32x2 %0,%1,%2;" : "=l"(d) : "l"(a), "l"(b)); return d;
}
__device__ __forceinline__ u64 pack2(float lo, float hi) {
    u64 r; asm("mov.b64 %0,{%1,%2};" : "=l"(r) : "f"(lo), "f"(hi)); return r;
}
__device__ __forceinline__ float2 unpack2(u64 v) {
    float lo, hi; asm("mov.b64 {%0,%1},%2;" : "=f"(lo), "=f"(hi) : "l"(v));
    return make_float2(lo, hi);
}

// Batch-independent precomputed tensors.
__device__ float g_M[HIDN * DD];    // [h][d]  M = bw @ w1^T
__device__ float g_w2t[HIDN * DD];  // [h][d]  w2^T
__device__ float g_beff[HIDN];

// ---------------------------------------------------------------------------
// prep: 18 CTAs x 256 threads, fully parallel.
// ---------------------------------------------------------------------------
__global__ void __launch_bounds__(256)
prep_kernel(const float* __restrict__ t,   const float* __restrict__ hw1,
            const float* __restrict__ hb1, const float* __restrict__ hw2,
            const float* __restrict__ hb2, const float* __restrict__ bw,
            const float* __restrict__ bb,  const float* __restrict__ w2) {
    __shared__ float hcode[HDIM];
    __shared__ float w1s[2][66];
    __shared__ float b1s[PREV];
    __shared__ float bws[HIDN * 65];

    int tid = threadIdx.x, lane = tid & 31, wrp = tid >> 5;
    int cta = blockIdx.x;

    if (cta == 17) {   // transpose w2 [d][h] -> [h][d]
        for (int i = tid; i < HIDN * DD; i += 256) {
            int d = i >> 7, h = i & 127;
            g_w2t[h * DD + d] = w2[i];
        }
        return;
    }

    if (tid < HDIM)
        hcode[tid] = tanhf(t[0] * hw1[tid] + hb1[tid]);
    for (int i = tid; i < HIDN * PREV; i += 256)
        bws[(i >> 6) * 65 + (i & 63)] = bw[i];
    __syncthreads();

    if (cta < 16) {
        int rbase = cta * 128;
#pragma unroll
        for (int rr = wrp; rr < 128; rr += 8) {
            int r = rbase + rr;
            const float* row = hw2 + r * HDIM;
            float acc = hcode[lane] * row[lane] + hcode[lane + 32] * row[lane + 32];
#pragma unroll
            for (int m = 16; m >= 1; m >>= 1)
                acc += __shfl_xor_sync(0xffffffffu, acc, m);
            if (lane == 0) w1s[rr >> 6][rr & 63] = acc + hb2[r];
        }
        __syncthreads();
        int dl = tid & 1, h = tid >> 1;
        int d  = 2 * cta + dl;
        float m = 0.f;
#pragma unroll
        for (int p = 0; p < PREV; p++)
            m += bws[h * 65 + p] * w1s[dl][p];
        g_M[h * DD + d] = m;
    } else {
#pragma unroll
        for (int rr = wrp; rr < PREV; rr += 8) {
            int r = DD * PREV + rr;
            const float* row = hw2 + r * HDIM;
            float acc = hcode[lane] * row[lane] + hcode[lane + 32] * row[lane + 32];
#pragma unroll
            for (int m = 16; m >= 1; m >>= 1)
                acc += __shfl_xor_sync(0xffffffffu, acc, m);
            if (lane == 0) b1s[rr] = acc + hb2[r];
        }
        __syncthreads();
        if (tid < HIDN) {
            float be = bb[tid];
#pragma unroll
            for (int p = 0; p < PREV; p++)
                be += bws[tid * 65 + p] * b1s[p];
            g_beff[tid] = be;
        }
    }
}

// ---------------------------------------------------------------------------
// main: 256 CTAs x 256 threads, 32 rows/CTA, 2 rows/thread, d-half split.
// Weight reads as LDS.128 (ulonglong2) with 2-stage prefetch; beff/c packed.
// ---------------------------------------------------------------------------
__global__ void __launch_bounds__(256, 2)
ode_main_kernel(const float* __restrict__ y,
                const float* __restrict__ b2,
                float* __restrict__ out) {
    __shared__ __align__(16) float Mt [HIDN * RSTR];
    __shared__ __align__(16) float W2t[HIDN * RSTR];
    __shared__ __align__(16) float xs [32 * RSTR];   // input tile; reused as output tile
    __shared__ float b2s[DD];

    int tid = threadIdx.x;

    // fill Mt / W2t: d 0..31 at row offsets 0..31 (contiguous, 16B-aligned rows)
    {
        const float4* ms = reinterpret_cast<const float4*>(g_M);
        const float4* ws = reinterpret_cast<const float4*>(g_w2t);
        for (int i = tid; i < HIDN * DD / 4; i += 256) {
            int col = i >> 3, q = i & 7;
            int off = col * RSTR + 4 * q;
            *reinterpret_cast<float4*>(Mt  + off) = ms[i];
            *reinterpret_cast<float4*>(W2t + off) = ws[i];
        }
    }
    if (tid < HIDN) Mt[tid * RSTR + 32] = g_beff[tid];
    if (tid < DD)   b2s[tid] = b2[tid];

    int rowbase = blockIdx.x * 32;
    for (int i = tid; i < 32 * 33; i += 256) {
        int r = i / 33, c = i - r * 33;
        xs[r * RSTR + c] = y[rowbase * 33 + i];
    }
    __syncthreads();

    // c[h] = sum_d M[h,d]*w2t[h,d]  -> Mt[h*RSTR+33]  (pairs with beff at +32)
    if (tid < HIDN) {
        const float* mr = Mt  + tid * RSTR;
        const float* wr = W2t + tid * RSTR;
        float c = 0.f;
#pragma unroll
        for (int k = 0; k < DD; k++) c += mr[k] * wr[k];
        Mt[tid * RSTR + 33] = c;
    }
    __syncthreads();

    int g2 = tid & 7;
    int dh = (tid >> 3) & 1;
    int rw = tid >> 4;          // 0..15 -> rows 2rw, 2rw+1
    int moff = dh * 16;

    u64 xp0[8], xp1[8];
    {
        const ulonglong2* xr0 = reinterpret_cast<const ulonglong2*>(xs + (2 * rw)     * RSTR + moff);
        const ulonglong2* xr1 = reinterpret_cast<const ulonglong2*>(xs + (2 * rw + 1) * RSTR + moff);
#pragma unroll
        for (int j = 0; j < 4; j++) {
            ulonglong2 v0 = xr0[j], v1 = xr1[j];
            xp0[2 * j] = v0.x; xp0[2 * j + 1] = v0.y;
            xp1[2 * j] = v1.x; xp1[2 * j + 1] = v1.y;
        }
    }

    u64 dxp0[8], dxp1[8];
#pragma unroll
    for (int j = 0; j < 8; j++) { dxp0[j] = 0ull; dxp1[j] = 0ull; }
    float dv0 = 0.f, dv1 = 0.f;

    // 2-stage pipeline: M prefetched one hh ahead; W loaded early in iteration.
    ulonglong2 mpf[2];
    {
        const ulonglong2* mr = reinterpret_cast<const ulonglong2*>(Mt + g2 * RSTR + moff);
        mpf[0] = mr[0]; mpf[1] = mr[1];
    }

#pragma unroll 2
    for (int hh = 0; hh < 16; hh++) {
        int col = hh * 8 + g2;
        // W for this hh (consumed at the end of the iteration)
        const ulonglong2* wr = reinterpret_cast<const ulonglong2*>(W2t + col * RSTR + moff);
        ulonglong2 w0 = wr[0], w1 = wr[1];
        // beff/c pair (one LDS.64 broadcast)
        float2 bc = *reinterpret_cast<const float2*>(Mt + col * RSTR + 32);

        u64 m0 = mpf[0].x, m1 = mpf[0].y, m2 = mpf[1].x, m3 = mpf[1].y;
        // prefetch M for hh+1
        if (hh < 15) {
            const ulonglong2* mn = reinterpret_cast<const ulonglong2*>(Mt + (col + 8) * RSTR + moff);
            mpf[0] = mn[0]; mpf[1] = mn[1];
        }

        u64 a0 = fma2(m0, xp0[0], 0ull);
        u64 a1 = fma2(m1, xp0[1], 0ull);
        u64 b0 = fma2(m0, xp1[0], 0ull);
        u64 b1 = fma2(m1, xp1[1], 0ull);
        a0 = fma2(m2, xp0[2], a0);
        a1 = fma2(m3, xp0[3], a1);
        b0 = fma2(m2, xp1[2], b0);
        b1 = fma2(m3, xp1[3], b1);
        {
            const ulonglong2* mr2 = reinterpret_cast<const ulonglong2*>(Mt + col * RSTR + moff);
            // second half of M slice (d 8..15 of this half): loaded fresh (cheap, L1-resident)
            ulonglong2 mq0 = mr2[2], mq1 = mr2[3];
            a0 = fma2(mq0.x, xp0[4], a0);
            a1 = fma2(mq0.y, xp0[5], a1);
            b0 = fma2(mq0.x, xp1[4], b0);
            b1 = fma2(mq0.y, xp1[5], b1);
            a0 = fma2(mq1.x, xp0[6], a0);
            a1 = fma2(mq1.y, xp0[7], a1);
            b0 = fma2(mq1.x, xp1[6], b0);
            b1 = fma2(mq1.y, xp1[7], b1);
        }
        float2 svA = unpack2(add2(a0, a1));
        float2 svB = unpack2(add2(b0, b1));
        u64 sp = pack2(svA.x + svA.y, svB.x + svB.y);
        sp = add2(sp, __shfl_xor_sync(0xffffffffu, sp, 8));  // merge d-halves
        float2 sv = unpack2(sp);
        float s0 = sv.x + bc.x, s1 = sv.y + bc.x;

        float r0 = __fdividef(2.f, __expf(2.f * s0) + 1.f);
        float r1 = __fdividef(2.f, __expf(2.f * s1) + 1.f);
        float av0 = 1.f - r0, av1 = 1.f - r1;     // tanh
        dv0 += r0 * (2.f - r0) * bc.y;
        dv1 += r1 * (2.f - r1) * bc.y;

        u64 aa0 = pack2(av0, av0), aa1 = pack2(av1, av1);
        const ulonglong2* wr2 = reinterpret_cast<const ulonglong2*>(W2t + col * RSTR + moff);
        ulonglong2 w2a = wr2[2], w2b = wr2[3];
        dxp0[0] = fma2(w0.x, aa0, dxp0[0]);
        dxp0[1] = fma2(w0.y, aa0, dxp0[1]);
        dxp1[0] = fma2(w0.x, aa1, dxp1[0]);
        dxp1[1] = fma2(w0.y, aa1, dxp1[1]);
        dxp0[2] = fma2(w1.x, aa0, dxp0[2]);
        dxp0[3] = fma2(w1.y, aa0, dxp0[3]);
        dxp1[2] = fma2(w1.x, aa1, dxp1[2]);
        dxp1[3] = fma2(w1.y, aa1, dxp1[3]);
        dxp0[4] = fma2(w2a.x, aa0, dxp0[4]);
        dxp0[5] = fma2(w2a.y, aa0, dxp0[5]);
        dxp1[4] = fma2(w2a.x, aa1, dxp1[4]);
        dxp1[5] = fma2(w2a.y, aa1, dxp1[5]);
        dxp0[6] = fma2(w2b.x, aa0, dxp0[6]);
        dxp0[7] = fma2(w2b.y, aa0, dxp0[7]);
        dxp1[6] = fma2(w2b.x, aa1, dxp1[6]);
        dxp1[7] = fma2(w2b.y, aa1, dxp1[7]);
    }

    // reduce over the 8 g2 groups (lane bits 0..2)
#pragma unroll
    for (int m = 1; m <= 4; m <<= 1) {
        u64 dvp = pack2(dv0, dv1);
        dvp = add2(dvp, __shfl_xor_sync(0xffffffffu, dvp, m));
        float2 dvv = unpack2(dvp);
        dv0 = dvv.x; dv1 = dvv.y;
#pragma unroll
        for (int j = 0; j < 8; j++) {
            dxp0[j] = add2(dxp0[j], __shfl_xor_sync(0xffffffffu, dxp0[j], m));
            dxp1[j] = add2(dxp1[j], __shfl_xor_sync(0xffffffffu, dxp1[j], m));
        }
    }

    __syncthreads();   // all xs input reads done; reuse xs as output tile
    if (g2 == 0) {
        float* o0 = xs + (2 * rw)     * RSTR + moff;
        float* o1 = xs + (2 * rw + 1) * RSTR + moff;
#pragma unroll
        for (int j = 0; j < 8; j++) {
            float2 v0 = unpack2(dxp0[j]);
            float2 v1 = unpack2(dxp1[j]);
            float bl = b2s[moff + 2 * j], bh = b2s[moff + 2 * j + 1];
            o0[2 * j] = v0.x + bl;  o0[2 * j + 1] = v0.y + bh;
            o1[2 * j] = v1.x + bl;  o1[2 * j + 1] = v1.y + bh;
        }
        if (dh == 0) {
            xs[(2 * rw)     * RSTR + 32] = -dv0;
            xs[(2 * rw + 1) * RSTR + 32] = -dv1;
        }
    }
    __syncthreads();
    for (int i = tid; i < 32 * 33; i += 256) {
        int r = i / 33, c = i - r * 33;
        out[rowbase * 33 + i] = xs[r * RSTR + c];
    }
}

// ---------------------------------------------------------------------------
// inputs: 0:y 1:t 2:hw1 3:hb1 4:hw2 5:hb2 6:bw 7:bb 8:w2 9:b2
// ---------------------------------------------------------------------------
extern "C" void kernel_launch(void* const* d_in, const int* in_sizes, int n_in,
                              void* d_out, int out_size) {
    const float* y   = (const float*)d_in[0];
    const float* t   = (const float*)d_in[1];
    const float* hw1 = (const float*)d_in[2];
    const float* hb1 = (const float*)d_in[3];
    const float* hw2 = (const float*)d_in[4];
    const float* hb2 = (const float*)d_in[5];
    const float* bw  = (const float*)d_in[6];
    const float* bb  = (const float*)d_in[7];
    const float* w2  = (const float*)d_in[8];
    const float* b2  = (const float*)d_in[9];
    float* out = (float*)d_out;

    prep_kernel<<<18, 256>>>(t, hw1, hb1, hw2, hb2, bw, bb, w2);
    ode_main_kernel<<<BATCH / 32, 256>>>(y, b2, out);
}